// round 1
// baseline (speedup 1.0000x reference)
#include <cuda_runtime.h>
#include <math.h>

#define HC 64
#define NF 64
#define NG 5
#define SL 20
#define ZD 148
#define BN_EPS 1e-5f
#define MAX_N 50000

// Scratch (allocation-free rule: __device__ globals)
__device__ float g_agg[MAX_N * NF];   // per-layer aggregation buffer
__device__ float g_sums[2 * NF];      // [0:64) sum, [64:128) sumsq

// ---------------------------------------------------------------------------
// zero scratch
__global__ void zero_kernel(int n_agg) {
    int i = blockIdx.x * blockDim.x + threadIdx.x;
    int stride = gridDim.x * blockDim.x;
    for (; i < n_agg; i += stride) g_agg[i] = 0.f;
    if (blockIdx.x == 0 && threadIdx.x < 2 * NF) g_sums[threadIdx.x] = 0.f;
}

// ---------------------------------------------------------------------------
// out = relu(h @ W + b)   [N,64] = [N,64] @ [64,64]
__global__ __launch_bounds__(256) void lin0_kernel(
    const float* __restrict__ h, const float* __restrict__ W,
    const float* __restrict__ b, float* __restrict__ out, int N)
{
    __shared__ float sW[64 * 64];
    __shared__ float sb[64];
    int tid = threadIdx.x;
    for (int i = tid; i < 64 * 64; i += 256) sW[i] = W[i];
    if (tid < 64) sb[tid] = b[tid];
    __syncthreads();

    int c = tid & 63, rr = tid >> 6;
    for (int r0 = blockIdx.x * 4; r0 < N; r0 += gridDim.x * 4) {
        int r = r0 + rr;
        if (r < N) {
            const float* hr = h + (size_t)r * 64;
            float acc = sb[c];
#pragma unroll 16
            for (int k = 0; k < 64; k++)
                acc = fmaf(__ldg(hr + k), sW[k * 64 + c], acc);
            out[(size_t)r * 64 + c] = fmaxf(acc, 0.f);
        }
    }
}

// ---------------------------------------------------------------------------
// Edge-message kernel: per tile of 64 edges, build z^T [148][64] in smem,
// GEMM against Wf/Ws [148][64] (in smem), epilogue sigmoid*softplus,
// atomicAdd into g_agg[dst].
// smem floats: Wf 9472 | Ws 9472 | zt 9472 | sea 320 | ssw 100 | ssb 20 |
//              sbf 64 | sbs 64 | (int) sdst 64 | ssrc 64
#define EDGE_SMEM_FLOATS (ZD*64*3 + 320 + 100 + 20 + 64 + 64)
#define EDGE_SMEM_BYTES  (EDGE_SMEM_FLOATS*4 + 128*4)

__global__ __launch_bounds__(256) void edge_kernel(
    const float* __restrict__ out, const int* __restrict__ ei,
    const float* __restrict__ eattr,
    const float* __restrict__ Wf, const float* __restrict__ bf,
    const float* __restrict__ Ws, const float* __restrict__ bs,
    const float* __restrict__ shw, const float* __restrict__ shb,
    int E)
{
    extern __shared__ float sm[];
    float* sWf = sm;                 // [148][64]
    float* sWs = sWf + ZD * 64;      // [148][64]
    float* zt  = sWs + ZD * 64;      // [148][64]  (z transposed: [k][edge])
    float* sea = zt + ZD * 64;       // [64][5]
    float* ssw = sea + 64 * NG;      // [5][20]
    float* ssb = ssw + NG * SL;      // [20]
    float* sbf = ssb + SL;           // [64]
    float* sbs = sbf + 64;           // [64]
    int*   sdst = (int*)(sbs + 64);  // [64]
    int*   ssrc = sdst + 64;         // [64]

    int tid = threadIdx.x;
    for (int i = tid; i < ZD * 64; i += 256) { sWf[i] = Wf[i]; sWs[i] = Ws[i]; }
    if (tid < NG * SL) ssw[tid] = shw[tid];
    if (tid < SL)      ssb[tid] = shb[tid];
    if (tid < 64)      { sbf[tid] = bf[tid]; sbs[tid] = bs[tid]; }
    __syncthreads();

    const int eg = tid & 15;   // edge group: edges eg*4 .. eg*4+3
    const int cg = tid >> 4;   // col group:  cols  cg*4 .. cg*4+3
    int ntiles = (E + 63) >> 6;

    for (int t = blockIdx.x; t < ntiles; t += gridDim.x) {
        int e0 = t << 6;
        if (tid < 64) {
            int e = e0 + tid;
            ssrc[tid] = (e < E) ? ei[e] : 0;
            sdst[tid] = (e < E) ? ei[E + e] : 0;
        }
        for (int i = tid; i < 64 * NG; i += 256) {
            long gidx = (long)e0 * NG + i;
            sea[i] = (gidx < (long)E * NG) ? eattr[gidx] : 0.f;
        }
        __syncthreads();

        // gather x_i (out[dst]) -> zt rows [0,64), x_j (out[src]) -> [64,128)
        // lanes vary edge -> conflict-free smem stores, L1 absorbs gmem gather
        for (int i = tid; i < 64 * 64; i += 256) {
            int e = i & 63, c = i >> 6;
            zt[c * 64 + e]        = __ldg(&out[(size_t)sdst[e] * 64 + c]);
            zt[(64 + c) * 64 + e] = __ldg(&out[(size_t)ssrc[e] * 64 + c]);
        }
        // ea -> zt rows [128,148)
        for (int i = tid; i < 64 * SL; i += 256) {
            int e = i & 63, s = i >> 6;
            float a = ssb[s];
#pragma unroll
            for (int g = 0; g < NG; g++) a = fmaf(sea[e * NG + g], ssw[g * SL + s], a);
            zt[(128 + s) * 64 + e] = fmaxf(a, 0.f);
        }
        __syncthreads();

        // GEMM: [64e x 148] @ [148 x 64c], two weight matrices simultaneously
        float accf[4][4], accs[4][4];
#pragma unroll
        for (int i = 0; i < 4; i++)
#pragma unroll
            for (int j = 0; j < 4; j++) {
                accf[i][j] = sbf[cg * 4 + j];
                accs[i][j] = sbs[cg * 4 + j];
            }
#pragma unroll 4
        for (int k = 0; k < ZD; k++) {
            float4 z4 = *(const float4*)&zt[k * 64 + eg * 4];
            float4 f4 = *(const float4*)&sWf[k * 64 + cg * 4];
            float4 s4 = *(const float4*)&sWs[k * 64 + cg * 4];
            float zz[4] = {z4.x, z4.y, z4.z, z4.w};
            float ff[4] = {f4.x, f4.y, f4.z, f4.w};
            float ws[4] = {s4.x, s4.y, s4.z, s4.w};
#pragma unroll
            for (int i = 0; i < 4; i++)
#pragma unroll
                for (int j = 0; j < 4; j++) {
                    accf[i][j] = fmaf(zz[i], ff[j], accf[i][j]);
                    accs[i][j] = fmaf(zz[i], ws[j], accs[i][j]);
                }
        }

        // epilogue: msg = sigmoid(f) * softplus(s); scatter-add
#pragma unroll
        for (int i = 0; i < 4; i++) {
            int e = eg * 4 + i;
            if (e0 + e < E) {
                int d = sdst[e];
#pragma unroll
                for (int j = 0; j < 4; j++) {
                    int c = cg * 4 + j;
                    float f = accf[i][j], s = accs[i][j];
                    float sig = 1.f / (1.f + expf(-f));
                    float sp  = fmaxf(s, 0.f) + log1pf(expf(-fabsf(s)));
                    atomicAdd(&g_agg[(size_t)d * 64 + c], sig * sp);
                }
            }
        }
        __syncthreads();   // protect smem reuse next tile
    }
}

// ---------------------------------------------------------------------------
// per-channel sum / sumsq over N rows of g_agg
__global__ __launch_bounds__(256) void bn_stats_kernel(int N) {
    __shared__ float s1[256], s2[256];
    int tid = threadIdx.x;
    int c = tid & 63;
    float s = 0.f, ss = 0.f;
    for (int r = blockIdx.x * 4 + (tid >> 6); r < N; r += gridDim.x * 4) {
        float v = g_agg[(size_t)r * 64 + c];
        s += v;
        ss = fmaf(v, v, ss);
    }
    s1[tid] = s; s2[tid] = ss;
    __syncthreads();
    if (tid < 64) {
        float a = s1[tid] + s1[tid + 64] + s1[tid + 128] + s1[tid + 192];
        float b = s2[tid] + s2[tid + 64] + s2[tid + 128] + s2[tid + 192];
        atomicAdd(&g_sums[tid], a);
        atomicAdd(&g_sums[64 + tid], b);
    }
}

// ---------------------------------------------------------------------------
// out = out + relu( BN(agg) + out )
__global__ __launch_bounds__(256) void bn_apply_kernel(
    const float* __restrict__ gamma, const float* __restrict__ beta,
    float* __restrict__ out, int N, float invN)
{
    int total = N * 64;
    int stride = gridDim.x * blockDim.x;
    for (int i = blockIdx.x * blockDim.x + threadIdx.x; i < total; i += stride) {
        int c = i & 63;
        float mean = g_sums[c] * invN;
        float var  = fmaf(-mean, mean, g_sums[64 + c] * invN);
        float inv  = rsqrtf(var + BN_EPS);
        float bn = (g_agg[i] - mean) * inv * gamma[c] + beta[c];
        float o = out[i];
        out[i] = o + fmaxf(bn + o, 0.f);
    }
}

// ---------------------------------------------------------------------------
extern "C" void kernel_launch(void* const* d_in, const int* in_sizes, int n_in,
                              void* d_out, int out_size)
{
    const float* h      = (const float*)d_in[0];
    const int*   ei     = (const int*)  d_in[1];
    // d_in[2] = edge_weight (unused by reference)
    const float* eattr  = (const float*)d_in[3];
    const float* lin0_w = (const float*)d_in[4];
    const float* lin0_b = (const float*)d_in[5];
    const float* shw    = (const float*)d_in[6];
    const float* shb    = (const float*)d_in[7];
    const float* linf_w = (const float*)d_in[8];
    const float* linf_b = (const float*)d_in[9];
    const float* lins_w = (const float*)d_in[10];
    const float* lins_b = (const float*)d_in[11];
    const float* gamma  = (const float*)d_in[12];
    const float* beta   = (const float*)d_in[13];

    int N = in_sizes[0] / HC;
    int E = in_sizes[1] / 2;
    float* out = (float*)d_out;

    cudaFuncSetAttribute(edge_kernel,
                         cudaFuncAttributeMaxDynamicSharedMemorySize,
                         EDGE_SMEM_BYTES);

    lin0_kernel<<<592, 256>>>(h, lin0_w, lin0_b, out, N);

    for (int l = 0; l < 2; l++) {
        zero_kernel<<<256, 256>>>(N * NF);
        edge_kernel<<<152, 256, EDGE_SMEM_BYTES>>>(
            out, ei, eattr,
            linf_w + (size_t)l * ZD * NF, linf_b + l * NF,
            lins_w + (size_t)l * ZD * NF, lins_b + l * NF,
            shw, shb, E);
        bn_stats_kernel<<<256, 256>>>(N);
        bn_apply_kernel<<<592, 256>>>(gamma + l * NF, beta + l * NF, out, N, 1.f / (float)N);
    }
}

// round 2
// speedup vs baseline: 3.0296x; 3.0296x over previous
#include <cuda_runtime.h>
#include <math.h>

#define HC 64
#define NF 64
#define NG 5
#define SL 20
#define ZD 148
#define BN_EPS 1e-5f
#define MAX_N 50000
#define MAX_E 800000

typedef unsigned long long ull;

// Scratch (allocation-free rule: __device__ globals)
__device__ __align__(16) float g_agg[MAX_N * NF];      // per-layer aggregation
__device__ __align__(16) float g_proj[MAX_N * 4 * NF]; // [N][Af|Bf|As|Bs]
__device__ __align__(16) float g_ea[(size_t)MAX_E * SL]; // relu(edge_attr@short_w)
__device__ __align__(16) float g_sums[2 * NF];         // sum / sumsq

// ---------------- packed f32x2 helpers ----------------
__device__ __forceinline__ ull fma2(ull a, ull b, ull c) {
    ull d;
    asm("fma.rn.f32x2 %0, %1, %2, %3;" : "=l"(d) : "l"(a), "l"(b), "l"(c));
    return d;
}
__device__ __forceinline__ ull add2(ull a, ull b) {
    ull d;
    asm("add.rn.f32x2 %0, %1, %2;" : "=l"(d) : "l"(a), "l"(b));
    return d;
}
__device__ __forceinline__ ull pack2(float v) {
    ull r;
    asm("mov.b64 %0, {%1, %1};" : "=l"(r) : "f"(v));
    return r;
}
__device__ __forceinline__ float2 unpack2(ull v) {
    float2 r;
    asm("mov.b64 {%0, %1}, %2;" : "=f"(r.x), "=f"(r.y) : "l"(v));
    return r;
}
__device__ __forceinline__ void red_add_v4(float* addr, float a, float b, float c, float d) {
    asm volatile("red.global.add.v4.f32 [%0], {%1, %2, %3, %4};"
                 :: "l"(addr), "f"(a), "f"(b), "f"(c), "f"(d) : "memory");
}
__device__ __forceinline__ float msg_fn(float f, float s) {
    float sig = __fdividef(1.f, 1.f + __expf(-f));
    float sp  = fmaxf(s, 0.f) + __logf(1.f + __expf(-fabsf(s)));
    return sig * sp;
}

// ---------------------------------------------------------------------------
__global__ __launch_bounds__(256) void zero_kernel(int n4) {
    float4 z = make_float4(0.f, 0.f, 0.f, 0.f);
    float4* a = (float4*)g_agg;
    int stride = gridDim.x * blockDim.x;
    for (int i = blockIdx.x * blockDim.x + threadIdx.x; i < n4; i += stride) a[i] = z;
    if (blockIdx.x == 0 && threadIdx.x < 2 * NF) g_sums[threadIdx.x] = 0.f;
}

// ---------------------------------------------------------------------------
// g_ea = relu(edge_attr @ short_w + short_b)   (layer-invariant, computed once)
__global__ __launch_bounds__(256) void ea_kernel(
    const float* __restrict__ attr, const float* __restrict__ sw,
    const float* __restrict__ sb, int E)
{
    __shared__ float w[NG * SL];
    __shared__ float b[SL];
    int tid = threadIdx.x;
    if (tid < NG * SL) w[tid] = sw[tid];
    if (tid < SL)      b[tid] = sb[tid];
    __syncthreads();
    int stride = gridDim.x * blockDim.x;
    for (int e = blockIdx.x * blockDim.x + tid; e < E; e += stride) {
        float a[NG];
#pragma unroll
        for (int g = 0; g < NG; g++) a[g] = __ldg(attr + (size_t)e * NG + g);
        float4* dst = (float4*)(g_ea + (size_t)e * SL);
#pragma unroll
        for (int q = 0; q < 5; q++) {
            float o[4];
#pragma unroll
            for (int j = 0; j < 4; j++) {
                float acc = b[q * 4 + j];
#pragma unroll
                for (int g = 0; g < NG; g++)
                    acc = fmaf(a[g], w[g * SL + q * 4 + j], acc);
                o[j] = fmaxf(acc, 0.f);
            }
            dst[q] = make_float4(o[0], o[1], o[2], o[3]);
        }
    }
}

// ---------------------------------------------------------------------------
// out = relu(h @ W + b)   [N,64]
__global__ __launch_bounds__(256) void lin0_kernel(
    const float* __restrict__ h, const float* __restrict__ W,
    const float* __restrict__ b, float* __restrict__ out, int N)
{
    __shared__ float sW[64 * 64];
    __shared__ float sb[64];
    int tid = threadIdx.x;
    for (int i = tid; i < 64 * 64; i += 256) sW[i] = W[i];
    if (tid < 64) sb[tid] = b[tid];
    __syncthreads();

    int c = tid & 63, rr = tid >> 6;
    for (int r0 = blockIdx.x * 4; r0 < N; r0 += gridDim.x * 4) {
        int r = r0 + rr;
        if (r < N) {
            const float* hr = h + (size_t)r * 64;
            float acc = sb[c];
#pragma unroll 16
            for (int k = 0; k < 64; k++)
                acc = fmaf(__ldg(hr + k), sW[k * 64 + c], acc);
            out[(size_t)r * 64 + c] = fmaxf(acc, 0.f);
        }
    }
}

// ---------------------------------------------------------------------------
// g_proj[n] = out[n] @ [W1f | W2f | W1s | W2s]  (+bf on cols 0-63, +bs on 128-191)
// Wf/Ws are [148][64] layer slices; W1 = rows 0-63 (dst part), W2 = rows 64-127 (src part)
__global__ __launch_bounds__(256) void node_proj_kernel(
    const float* __restrict__ out,
    const float* __restrict__ Wf, const float* __restrict__ bf,
    const float* __restrict__ Ws, const float* __restrict__ bs,
    int N)
{
    __shared__ __align__(16) float sOut[16 * 64];
    int tid = threadIdx.x;
    int c = tid;
    const float* base; int col; float bias;
    if (c < 64)       { base = Wf;           col = c;        bias = __ldg(bf + c); }
    else if (c < 128) { base = Wf + 64 * 64; col = c - 64;   bias = 0.f; }
    else if (c < 192) { base = Ws;           col = c - 128;  bias = __ldg(bs + c - 128); }
    else              { base = Ws + 64 * 64; col = c - 192;  bias = 0.f; }
    float w[64];
#pragma unroll
    for (int k = 0; k < 64; k++) w[k] = __ldg(base + k * 64 + col);

    for (int r0 = blockIdx.x * 16; r0 < N; r0 += gridDim.x * 16) {
        __syncthreads();
        for (int i = tid; i < 16 * 16; i += 256) {
            int r = i >> 4, q = i & 15;
            int rr = r0 + r;
            float4 v = (rr < N) ? ((const float4*)out)[(size_t)rr * 16 + q]
                                : make_float4(0.f, 0.f, 0.f, 0.f);
            ((float4*)sOut)[r * 16 + q] = v;
        }
        __syncthreads();
        float acc[16];
#pragma unroll
        for (int r = 0; r < 16; r++) acc[r] = bias;
#pragma unroll
        for (int k4 = 0; k4 < 16; k4++) {
#pragma unroll
            for (int r = 0; r < 16; r++) {
                float4 z = ((const float4*)sOut)[r * 16 + k4];
                acc[r] = fmaf(z.x, w[k4 * 4 + 0], acc[r]);
                acc[r] = fmaf(z.y, w[k4 * 4 + 1], acc[r]);
                acc[r] = fmaf(z.z, w[k4 * 4 + 2], acc[r]);
                acc[r] = fmaf(z.w, w[k4 * 4 + 3], acc[r]);
            }
        }
#pragma unroll
        for (int r = 0; r < 16; r++) {
            int rr = r0 + r;
            if (rr < N) g_proj[(size_t)rr * 256 + c] = acc[r];
        }
    }
}

// ---------------------------------------------------------------------------
// Edge kernel: f = proj[dst][0:64] + proj[src][64:128] + ea@W3f
//              s = proj[dst][128:192] + proj[src][192:256] + ea@W3s
// msg = sigmoid(f)*softplus(s); red.v4 into g_agg[dst]
// Warp handles 2 edges: lanes 0-15 -> edge e0, 16-31 -> edge e0+1;
// lane t in [0,16) owns 4 channels c = 4t..4t+3.
__global__ __launch_bounds__(256) void edge_kernel(
    const int* __restrict__ ei,
    const float* __restrict__ W3f, const float* __restrict__ W3s,
    int E)
{
    __shared__ __align__(16) float sF[SL * 64];
    __shared__ __align__(16) float sS[SL * 64];
    int tid = threadIdx.x;
    for (int i = tid; i < SL * 64; i += 256) { sF[i] = W3f[i]; sS[i] = W3s[i]; }
    __syncthreads();

    int lane = tid & 31;
    int t = lane & 15;
    int half = lane >> 4;
    long gw = ((long)blockIdx.x * 256 + tid) >> 5;
    long nw = ((long)gridDim.x * 256) >> 5;
    const ulonglong2* wfp = (const ulonglong2*)sF;
    const ulonglong2* wsp = (const ulonglong2*)sS;
    long npairs = ((long)E + 1) >> 1;

    for (long p = gw; p < npairs; p += nw) {
        long e = 2 * p + half;
        bool valid = e < E;
        long ec = valid ? e : 0;
        int src = __ldg(ei + ec);
        int dst = __ldg(ei + E + ec);

        // ea row -> registers
        const float4* ear = (const float4*)(g_ea + ec * SL);
        float4 a0 = __ldg(ear + 0), a1 = __ldg(ear + 1), a2 = __ldg(ear + 2),
               a3 = __ldg(ear + 3), a4 = __ldg(ear + 4);
        float ea[20] = {a0.x, a0.y, a0.z, a0.w, a1.x, a1.y, a1.z, a1.w,
                        a2.x, a2.y, a2.z, a2.w, a3.x, a3.y, a3.z, a3.w,
                        a4.x, a4.y, a4.z, a4.w};

        // gather node projections (each 16B, packed f32x2 pairs)
        const ulonglong2* pd = (const ulonglong2*)(g_proj + (size_t)dst * 256);
        const ulonglong2* ps = (const ulonglong2*)(g_proj + (size_t)src * 256);
        ulonglong2 afi = __ldg(pd + t);
        ulonglong2 bfj = __ldg(ps + 16 + t);
        ulonglong2 asi = __ldg(pd + 32 + t);
        ulonglong2 bsj = __ldg(ps + 48 + t);

        ull f01 = add2(afi.x, bfj.x), f23 = add2(afi.y, bfj.y);
        ull s01 = add2(asi.x, bsj.x), s23 = add2(asi.y, bsj.y);

#pragma unroll
        for (int k = 0; k < 20; k++) {
            ull e2 = pack2(ea[k]);
            ulonglong2 wf = wfp[k * 16 + t];
            ulonglong2 ws = wsp[k * 16 + t];
            f01 = fma2(e2, wf.x, f01);
            f23 = fma2(e2, wf.y, f23);
            s01 = fma2(e2, ws.x, s01);
            s23 = fma2(e2, ws.y, s23);
        }

        float2 F0 = unpack2(f01), F1 = unpack2(f23);
        float2 S0 = unpack2(s01), S1 = unpack2(s23);
        float m0 = msg_fn(F0.x, S0.x);
        float m1 = msg_fn(F0.y, S0.y);
        float m2 = msg_fn(F1.x, S1.x);
        float m3 = msg_fn(F1.y, S1.y);

        if (valid)
            red_add_v4(&g_agg[(size_t)dst * 64 + t * 4], m0, m1, m2, m3);
    }
}

// ---------------------------------------------------------------------------
__global__ __launch_bounds__(256) void bn_stats_kernel(int N) {
    __shared__ float4 s1[256], s2[256];
    int tid = threadIdx.x;
    const float4* a4 = (const float4*)g_agg;
    int total = N * 16;
    float4 s = make_float4(0.f, 0.f, 0.f, 0.f);
    float4 q = make_float4(0.f, 0.f, 0.f, 0.f);
    int stride = gridDim.x * 256;
    for (int i = blockIdx.x * 256 + tid; i < total; i += stride) {
        float4 v = a4[i];
        s.x += v.x; s.y += v.y; s.z += v.z; s.w += v.w;
        q.x = fmaf(v.x, v.x, q.x); q.y = fmaf(v.y, v.y, q.y);
        q.z = fmaf(v.z, v.z, q.z); q.w = fmaf(v.w, v.w, q.w);
    }
    s1[tid] = s; s2[tid] = q;
    __syncthreads();
    if (tid < 16) {
        float4 S = s1[tid], Q = s2[tid];
#pragma unroll
        for (int j = 1; j < 16; j++) {
            float4 a = s1[tid + 16 * j], b = s2[tid + 16 * j];
            S.x += a.x; S.y += a.y; S.z += a.z; S.w += a.w;
            Q.x += b.x; Q.y += b.y; Q.z += b.z; Q.w += b.w;
        }
        int c0 = tid * 4;
        atomicAdd(&g_sums[c0 + 0], S.x);
        atomicAdd(&g_sums[c0 + 1], S.y);
        atomicAdd(&g_sums[c0 + 2], S.z);
        atomicAdd(&g_sums[c0 + 3], S.w);
        atomicAdd(&g_sums[64 + c0 + 0], Q.x);
        atomicAdd(&g_sums[64 + c0 + 1], Q.y);
        atomicAdd(&g_sums[64 + c0 + 2], Q.z);
        atomicAdd(&g_sums[64 + c0 + 3], Q.w);
    }
}

// ---------------------------------------------------------------------------
// out = out + relu( BN(agg) + out )
__global__ __launch_bounds__(256) void bn_apply_kernel(
    const float* __restrict__ gamma, const float* __restrict__ beta,
    float* __restrict__ out, int N, float invN)
{
    int tid = threadIdx.x;
    int c0 = (tid & 15) * 4;
    float mul[4], add[4];
#pragma unroll
    for (int j = 0; j < 4; j++) {
        float mean = g_sums[c0 + j] * invN;
        float var  = fmaf(-mean, mean, g_sums[64 + c0 + j] * invN);
        float inv  = rsqrtf(var + BN_EPS);
        float m = inv * __ldg(gamma + c0 + j);
        mul[j] = m;
        add[j] = __ldg(beta + c0 + j) - mean * m;
    }
    float4* o4 = (float4*)out;
    const float4* a4 = (const float4*)g_agg;
    int total = N * 16;
    int stride = gridDim.x * 256;
    for (int i = blockIdx.x * 256 + tid; i < total; i += stride) {
        float4 a = a4[i], o = o4[i], r;
        float bn;
        bn = fmaf(a.x, mul[0], add[0]); r.x = o.x + fmaxf(bn + o.x, 0.f);
        bn = fmaf(a.y, mul[1], add[1]); r.y = o.y + fmaxf(bn + o.y, 0.f);
        bn = fmaf(a.z, mul[2], add[2]); r.z = o.z + fmaxf(bn + o.z, 0.f);
        bn = fmaf(a.w, mul[3], add[3]); r.w = o.w + fmaxf(bn + o.w, 0.f);
        o4[i] = r;
    }
}

// ---------------------------------------------------------------------------
extern "C" void kernel_launch(void* const* d_in, const int* in_sizes, int n_in,
                              void* d_out, int out_size)
{
    const float* h      = (const float*)d_in[0];
    const int*   ei     = (const int*)  d_in[1];
    // d_in[2] = edge_weight (unused by reference)
    const float* eattr  = (const float*)d_in[3];
    const float* lin0_w = (const float*)d_in[4];
    const float* lin0_b = (const float*)d_in[5];
    const float* shw    = (const float*)d_in[6];
    const float* shb    = (const float*)d_in[7];
    const float* linf_w = (const float*)d_in[8];
    const float* linf_b = (const float*)d_in[9];
    const float* lins_w = (const float*)d_in[10];
    const float* lins_b = (const float*)d_in[11];
    const float* gamma  = (const float*)d_in[12];
    const float* beta   = (const float*)d_in[13];

    int N = in_sizes[0] / HC;
    int E = in_sizes[1] / 2;
    float* out = (float*)d_out;

    ea_kernel<<<1184, 256>>>(eattr, shw, shb, E);
    lin0_kernel<<<592, 256>>>(h, lin0_w, lin0_b, out, N);

    for (int l = 0; l < 2; l++) {
        const float* Wf = linf_w + (size_t)l * ZD * NF;
        const float* Ws = lins_w + (size_t)l * ZD * NF;
        zero_kernel<<<592, 256>>>(N * 16);
        node_proj_kernel<<<592, 256>>>(out, Wf, linf_b + l * NF,
                                       Ws, lins_b + l * NF, N);
        edge_kernel<<<1184, 256>>>(ei, Wf + 128 * NF, Ws + 128 * NF, E);
        bn_stats_kernel<<<592, 256>>>(N);
        bn_apply_kernel<<<592, 256>>>(gamma + l * NF, beta + l * NF, out, N, 1.f / (float)N);
    }
}